// round 4
// baseline (speedup 1.0000x reference)
#include <cuda_runtime.h>

#define B_  64
#define T_  8192
#define D_  128
#define H1_ 128
#define H2_ 64
#define K_  9

// Emissions scratch (B*T, K) fp32 = 18.9 MB (device global; no allocs allowed).
__device__ float g_em[(size_t)B_ * T_ * K_];

// ---------------------------------------------------------------------------
// Kernel 1: fused MLP -> emissions. 64 tokens / block, 256 threads.
// All shared memory STATIC (<48KB).
// ---------------------------------------------------------------------------
#define TOK 64
#define AS  132   // row stride for 128-wide activation rows (float4 aligned)

__global__ void __launch_bounds__(256) mlp_kernel(
    const float* __restrict__ x,  const float* __restrict__ W1, const float* __restrict__ b1,
    const float* __restrict__ W2, const float* __restrict__ b2,
    const float* __restrict__ W3, const float* __restrict__ b3)
{
    __shared__ float sA[TOK * AS];   // 8448 fl: x rows -> h1 rows -> h2 rows
    __shared__ float sW[2048];       // W chunk (16 rows x 128, or 16 x 64)
    __shared__ float sW3[576];
    __shared__ float sB1[128];
    __shared__ float sB2[64];
    __shared__ float sB3[16];

    const int tid = threadIdx.x;
    const size_t nb = (size_t)blockIdx.x * TOK;

    // ---- load x tile row-major: sA[tok][d] ----
    {
        const float4* xv = (const float4*)(x + nb * D_);
        #pragma unroll
        for (int it = 0; it < 8; ++it) {
            int v   = tid + it * 256;      // 0..2047 float4
            int tok = v >> 5;              // 32 float4 per token
            int d4  = v & 31;
            *(float4*)&sA[tok * AS + d4 * 4] = xv[v];
        }
    }
    if (tid < 128) sB1[tid] = b1[tid];
    if (tid < 64)  sB2[tid] = b2[tid];
    if (tid < 9)   sB3[tid] = b3[tid];
    for (int k = tid; k < 576; k += 256) sW3[k] = W3[k];

    // ================= stage 1: h1 = relu(x @ W1 + b1) =================
    {
        const int tx = tid & 31, ty = tid >> 5;
        const int o0 = tx * 4, t0 = ty * 8;
        float acc[8][4];
        #pragma unroll
        for (int i = 0; i < 8; ++i)
            #pragma unroll
            for (int j = 0; j < 4; ++j) acc[i][j] = 0.f;

        const float4* w1v = (const float4*)W1;
        float4* sWv = (float4*)sW;
        for (int p = 0; p < 8; ++p) {          // 8 chunks of 16 k-rows
            __syncthreads();
            sWv[tid]       = w1v[p * 512 + tid];
            sWv[tid + 256] = w1v[p * 512 + tid + 256];
            __syncthreads();
            #pragma unroll
            for (int kl = 0; kl < 16; ++kl) {
                const int k = p * 16 + kl;
                float4 w = *(const float4*)&sW[kl * 128 + o0];
                float a[8];
                #pragma unroll
                for (int i = 0; i < 8; ++i) a[i] = sA[(t0 + i) * AS + k];
                #pragma unroll
                for (int i = 0; i < 8; ++i) {
                    acc[i][0] = fmaf(a[i], w.x, acc[i][0]);
                    acc[i][1] = fmaf(a[i], w.y, acc[i][1]);
                    acc[i][2] = fmaf(a[i], w.z, acc[i][2]);
                    acc[i][3] = fmaf(a[i], w.w, acc[i][3]);
                }
            }
        }
        __syncthreads();
        float4 bb = *(const float4*)&sB1[o0];
        #pragma unroll
        for (int i = 0; i < 8; ++i) {
            float4 v;
            v.x = acc[i][0] + bb.x; v.x = v.x > 0.f ? v.x : 0.f;
            v.y = acc[i][1] + bb.y; v.y = v.y > 0.f ? v.y : 0.f;
            v.z = acc[i][2] + bb.z; v.z = v.z > 0.f ? v.z : 0.f;
            v.w = acc[i][3] + bb.w; v.w = v.w > 0.f ? v.w : 0.f;
            *(float4*)&sA[(t0 + i) * AS + o0] = v;   // h1 row-major
        }
    }

    // ================= stage 2: h2 = relu(h1 @ W2 + b2) =================
    {
        const int tx = tid & 15, ty = tid >> 4;
        const int o0 = tx * 4, t0 = ty * 4;
        float acc[4][4];
        #pragma unroll
        for (int i = 0; i < 4; ++i)
            #pragma unroll
            for (int j = 0; j < 4; ++j) acc[i][j] = 0.f;

        const float4* w2v = (const float4*)W2;
        float4* sWv = (float4*)sW;
        for (int p = 0; p < 8; ++p) {
            __syncthreads();
            sWv[tid] = w2v[p * 256 + tid];     // 16x64 = 256 float4
            __syncthreads();
            #pragma unroll
            for (int kl = 0; kl < 16; ++kl) {
                const int k = p * 16 + kl;
                float4 w = *(const float4*)&sW[kl * 64 + o0];
                float a[4];
                #pragma unroll
                for (int i = 0; i < 4; ++i) a[i] = sA[(t0 + i) * AS + k];
                #pragma unroll
                for (int i = 0; i < 4; ++i) {
                    acc[i][0] = fmaf(a[i], w.x, acc[i][0]);
                    acc[i][1] = fmaf(a[i], w.y, acc[i][1]);
                    acc[i][2] = fmaf(a[i], w.z, acc[i][2]);
                    acc[i][3] = fmaf(a[i], w.w, acc[i][3]);
                }
            }
        }
        __syncthreads();
        float4 bb = *(const float4*)&sB2[o0];
        #pragma unroll
        for (int i = 0; i < 4; ++i) {
            float4 v;
            v.x = acc[i][0] + bb.x; v.x = v.x > 0.f ? v.x : 0.f;
            v.y = acc[i][1] + bb.y; v.y = v.y > 0.f ? v.y : 0.f;
            v.z = acc[i][2] + bb.z; v.z = v.z > 0.f ? v.z : 0.f;
            v.w = acc[i][3] + bb.w; v.w = v.w > 0.f ? v.w : 0.f;
            *(float4*)&sA[(t0 + i) * AS + o0] = v;   // h2 row-major (cols 0..63)
        }
    }
    __syncthreads();

    // ================= stage 3: em = h2 @ W3 + b3 =================
    if (tid < TOK) {
        const int tok = tid;
        float e[9];
        #pragma unroll
        for (int j = 0; j < 9; ++j) e[j] = 0.f;
        for (int k = 0; k < 64; ++k) {
            float h = sA[tok * AS + k];
            #pragma unroll
            for (int j = 0; j < 9; ++j)
                e[j] = fmaf(h, sW3[k * 9 + j], e[j]);
        }
        float* dst = g_em + (nb + tok) * K_;
        #pragma unroll
        for (int j = 0; j < 9; ++j) dst[j] = e[j] + sB3[j];
    }
}

// ---------------------------------------------------------------------------
// Kernel 2: Viterbi forward + backtrack. One warp per batch element.
// Backpointers nibble-packed (5 bytes/step) in STATIC smem.
// OUTPUT IS WRITTEN AS FLOAT32 VALUES (harness __output__ dtype).
// ---------------------------------------------------------------------------
__global__ void __launch_bounds__(32) viterbi_kernel(
    const float* __restrict__ st, const float* __restrict__ et,
    const float* __restrict__ trans, float* __restrict__ out)
{
    __shared__ float sEm[2 * 288];                 // double-buffered emission chunks
    __shared__ unsigned char sBpN[T_ * 5];         // 40960 B nibble-packed bps

    const int lane = threadIdx.x;
    const int b = blockIdx.x;
    const float* emb = g_em + (size_t)b * T_ * K_;
    const bool active = lane < K_;

    float tcol[K_];
    #pragma unroll
    for (int i = 0; i < K_; ++i) tcol[i] = active ? trans[i * K_ + lane] : 0.f;

    // score0 = start_trans + em[:,0]  (reference add order)
    float s = active ? (st[lane] + emb[lane]) : 0.f;

    // preload chunk 0 (steps t=1..32 -> 288 floats, linear layout)
    #pragma unroll
    for (int k = 0; k < 9; ++k) sEm[lane + k * 32] = emb[9 + lane + k * 32];
    __syncwarp();

    int buf = 0;
    for (int c = 0; c < 256; ++c) {
        const int t0 = 1 + c * 32;
        const int nsteps = min(32, T_ - t0);
        const int t0n = t0 + 32;
        const int nnext = (t0n < T_) ? min(32, T_ - t0n) : 0;

        float pref[9];
        #pragma unroll
        for (int k = 0; k < 9; ++k) {
            int idx = lane + k * 32;
            pref[k] = (idx < nnext * K_) ? emb[(size_t)t0n * K_ + idx] : 0.f;
        }

        const float* cur = sEm + buf * 288;
        for (int q = 0; q < nsteps; ++q) {
            const int t = t0 + q;
            float e = active ? cur[q * K_ + lane] : 0.f;
            float cd[9];
            #pragma unroll
            for (int i = 0; i < 9; ++i) {
                float si = __shfl_sync(0xffffffffu, s, i);
                cd[i] = (si + tcol[i]) + e;     // exact reference add order
            }
            float m01 = fmaxf(cd[0], cd[1]);
            float m23 = fmaxf(cd[2], cd[3]);
            float m45 = fmaxf(cd[4], cd[5]);
            float m67 = fmaxf(cd[6], cd[7]);
            float m = fmaxf(fmaxf(fmaxf(m01, m23), fmaxf(m45, m67)), cd[8]);
            int bp = 8;
            #pragma unroll
            for (int i = 7; i >= 0; --i) bp = (cd[i] == m) ? i : bp;  // first-max

            int bpn = __shfl_down_sync(0xffffffffu, bp, 1);
            if (active && ((lane & 1) == 0)) {
                unsigned char byte = (lane == 8)
                    ? (unsigned char)bp
                    : (unsigned char)(bp | (bpn << 4));
                sBpN[t * 5 + (lane >> 1)] = byte;
            }
            if (active) s = m;
        }
        __syncwarp();
        buf ^= 1;
        float* nxt = sEm + buf * 288;
        #pragma unroll
        for (int k = 0; k < 9; ++k) nxt[lane + k * 32] = pref[k];
        __syncwarp();
    }

    // last = argmax(final + end_trans), first-max semantics
    float fin = active ? (s + et[lane]) : -3.402823466e+38f;
    float best = __shfl_sync(0xffffffffu, fin, 0);
    int last = 0;
    #pragma unroll
    for (int j = 1; j < 9; ++j) {
        float v = __shfl_sync(0xffffffffu, fin, j);
        if (v > best) { best = v; last = j; }
    }

    // backtrack (lane 0): chase nibbles in smem, write FLOAT tags
    if (lane == 0) {
        float* ob = out + (size_t)b * T_;
        int tag = last;
        ob[T_ - 1] = (float)tag;
        for (int t = T_ - 1; t >= 1; --t) {
            unsigned int byte = sBpN[t * 5 + (tag >> 1)];
            tag = (int)((byte >> ((tag & 1) * 4)) & 0xF);
            ob[t - 1] = (float)tag;
        }
    }
}

// ---------------------------------------------------------------------------
extern "C" void kernel_launch(void* const* d_in, const int* in_sizes, int n_in,
                              void* d_out, int out_size)
{
    // Input identification by element count; defaults = setup_inputs dict
    // order. The three 9-element vectors keep relative order: b3, st, et.
    int ix = 0, iW1 = 1, ib1 = 2, iW2 = 3, ib2 = 4, iW3 = 5, itr = 9;
    int nine[3] = {6, 7, 8};
    int n9 = 0;
    for (int i = 0; i < n_in; ++i) {
        long long s = in_sizes[i];
        if (s == 67108864LL)      ix  = i;
        else if (s == 16384)      iW1 = i;
        else if (s == 128)        ib1 = i;
        else if (s == 8192)       iW2 = i;
        else if (s == 64)         ib2 = i;
        else if (s == 576)        iW3 = i;
        else if (s == 81)         itr = i;
        else if (s == 9) { if (n9 < 3) nine[n9++] = i; }
    }
    const float* x  = (const float*)d_in[ix];
    const float* W1 = (const float*)d_in[iW1];
    const float* b1 = (const float*)d_in[ib1];
    const float* W2 = (const float*)d_in[iW2];
    const float* b2 = (const float*)d_in[ib2];
    const float* W3 = (const float*)d_in[iW3];
    const float* b3 = (const float*)d_in[nine[0]];
    const float* st = (const float*)d_in[nine[1]];
    const float* et = (const float*)d_in[nine[2]];
    const float* tr = (const float*)d_in[itr];
    float* out = (float*)d_out;   // __output__ dtype: float32

    mlp_kernel<<<(B_ * T_) / TOK, 256>>>(x, W1, b1, W2, b2, W3, b3);
    viterbi_kernel<<<B_, 32>>>(st, et, tr, out);
}

// round 5
// speedup vs baseline: 1.1948x; 1.1948x over previous
#include <cuda_runtime.h>

#define B_  64
#define T_  8192
#define D_  128
#define H1_ 128
#define H2_ 64
#define K_  9

// Emissions scratch (B*T, K) fp32 = 18.9 MB (device global; no allocs allowed).
__device__ float g_em[(size_t)B_ * T_ * K_];

// ---------------------------------------------------------------------------
// Kernel 1: fused MLP -> emissions. 64 tokens / block, 256 threads.
// (unchanged from the passing round-4 version)
// ---------------------------------------------------------------------------
#define TOK 64
#define AS  132

__global__ void __launch_bounds__(256) mlp_kernel(
    const float* __restrict__ x,  const float* __restrict__ W1, const float* __restrict__ b1,
    const float* __restrict__ W2, const float* __restrict__ b2,
    const float* __restrict__ W3, const float* __restrict__ b3)
{
    __shared__ float sA[TOK * AS];
    __shared__ float sW[2048];
    __shared__ float sW3[576];
    __shared__ float sB1[128];
    __shared__ float sB2[64];
    __shared__ float sB3[16];

    const int tid = threadIdx.x;
    const size_t nb = (size_t)blockIdx.x * TOK;

    {
        const float4* xv = (const float4*)(x + nb * D_);
        #pragma unroll
        for (int it = 0; it < 8; ++it) {
            int v   = tid + it * 256;
            int tok = v >> 5;
            int d4  = v & 31;
            *(float4*)&sA[tok * AS + d4 * 4] = xv[v];
        }
    }
    if (tid < 128) sB1[tid] = b1[tid];
    if (tid < 64)  sB2[tid] = b2[tid];
    if (tid < 9)   sB3[tid] = b3[tid];
    for (int k = tid; k < 576; k += 256) sW3[k] = W3[k];

    // stage 1
    {
        const int tx = tid & 31, ty = tid >> 5;
        const int o0 = tx * 4, t0 = ty * 8;
        float acc[8][4];
        #pragma unroll
        for (int i = 0; i < 8; ++i)
            #pragma unroll
            for (int j = 0; j < 4; ++j) acc[i][j] = 0.f;

        const float4* w1v = (const float4*)W1;
        float4* sWv = (float4*)sW;
        for (int p = 0; p < 8; ++p) {
            __syncthreads();
            sWv[tid]       = w1v[p * 512 + tid];
            sWv[tid + 256] = w1v[p * 512 + tid + 256];
            __syncthreads();
            #pragma unroll
            for (int kl = 0; kl < 16; ++kl) {
                const int k = p * 16 + kl;
                float4 w = *(const float4*)&sW[kl * 128 + o0];
                float a[8];
                #pragma unroll
                for (int i = 0; i < 8; ++i) a[i] = sA[(t0 + i) * AS + k];
                #pragma unroll
                for (int i = 0; i < 8; ++i) {
                    acc[i][0] = fmaf(a[i], w.x, acc[i][0]);
                    acc[i][1] = fmaf(a[i], w.y, acc[i][1]);
                    acc[i][2] = fmaf(a[i], w.z, acc[i][2]);
                    acc[i][3] = fmaf(a[i], w.w, acc[i][3]);
                }
            }
        }
        __syncthreads();
        float4 bb = *(const float4*)&sB1[o0];
        #pragma unroll
        for (int i = 0; i < 8; ++i) {
            float4 v;
            v.x = acc[i][0] + bb.x; v.x = v.x > 0.f ? v.x : 0.f;
            v.y = acc[i][1] + bb.y; v.y = v.y > 0.f ? v.y : 0.f;
            v.z = acc[i][2] + bb.z; v.z = v.z > 0.f ? v.z : 0.f;
            v.w = acc[i][3] + bb.w; v.w = v.w > 0.f ? v.w : 0.f;
            *(float4*)&sA[(t0 + i) * AS + o0] = v;
        }
    }

    // stage 2
    {
        const int tx = tid & 15, ty = tid >> 4;
        const int o0 = tx * 4, t0 = ty * 4;
        float acc[4][4];
        #pragma unroll
        for (int i = 0; i < 4; ++i)
            #pragma unroll
            for (int j = 0; j < 4; ++j) acc[i][j] = 0.f;

        const float4* w2v = (const float4*)W2;
        float4* sWv = (float4*)sW;
        for (int p = 0; p < 8; ++p) {
            __syncthreads();
            sWv[tid] = w2v[p * 256 + tid];
            __syncthreads();
            #pragma unroll
            for (int kl = 0; kl < 16; ++kl) {
                const int k = p * 16 + kl;
                float4 w = *(const float4*)&sW[kl * 64 + o0];
                float a[4];
                #pragma unroll
                for (int i = 0; i < 4; ++i) a[i] = sA[(t0 + i) * AS + k];
                #pragma unroll
                for (int i = 0; i < 4; ++i) {
                    acc[i][0] = fmaf(a[i], w.x, acc[i][0]);
                    acc[i][1] = fmaf(a[i], w.y, acc[i][1]);
                    acc[i][2] = fmaf(a[i], w.z, acc[i][2]);
                    acc[i][3] = fmaf(a[i], w.w, acc[i][3]);
                }
            }
        }
        __syncthreads();
        float4 bb = *(const float4*)&sB2[o0];
        #pragma unroll
        for (int i = 0; i < 4; ++i) {
            float4 v;
            v.x = acc[i][0] + bb.x; v.x = v.x > 0.f ? v.x : 0.f;
            v.y = acc[i][1] + bb.y; v.y = v.y > 0.f ? v.y : 0.f;
            v.z = acc[i][2] + bb.z; v.z = v.z > 0.f ? v.z : 0.f;
            v.w = acc[i][3] + bb.w; v.w = v.w > 0.f ? v.w : 0.f;
            *(float4*)&sA[(t0 + i) * AS + o0] = v;
        }
    }
    __syncthreads();

    // stage 3
    if (tid < TOK) {
        const int tok = tid;
        float e[9];
        #pragma unroll
        for (int j = 0; j < 9; ++j) e[j] = 0.f;
        for (int k = 0; k < 64; ++k) {
            float h = sA[tok * AS + k];
            #pragma unroll
            for (int j = 0; j < 9; ++j)
                e[j] = fmaf(h, sW3[k * 9 + j], e[j]);
        }
        float* dst = g_em + (nb + tok) * K_;
        #pragma unroll
        for (int j = 0; j < 9; ++j) dst[j] = e[j] + sB3[j];
    }
}

// ---------------------------------------------------------------------------
// Kernel 2: Viterbi. One block (2 warps) per batch element.
//   warp0: score chain (e added AFTER max — bitwise identical by RN monotonicity)
//   warp1: trails one 32-step chunk; recomputes cd in exact ref order, finds
//          first i with cd[i]==s_t[j] (== jnp.argmax), writes nibble bps.
//   backtrack: 128 jump-chunks of 64 steps, 3-phase parallel (exact chase).
// ---------------------------------------------------------------------------
#define RSLOTS 72            // ring modulus (needs >= 65, no collision for lag 33..64)
#define RPAD   (RSLOTS * 12 + 32)

__device__ __forceinline__ int nib_get(const unsigned char* bpn, int t, int tag) {
    unsigned v = bpn[t * 5 + (tag >> 1)];
    return (int)((v >> ((tag & 1) * 4)) & 0xF);
}

__global__ void __launch_bounds__(64) viterbi_kernel(
    const float* __restrict__ st, const float* __restrict__ et,
    const float* __restrict__ trans, float* __restrict__ out)
{
    __shared__ unsigned char sBpN[T_ * 5];   // 40960 B nibble-packed backpointers
    __shared__ float sRing[RPAD];            // s-vector ring, 12 floats/slot (+pad)
    __shared__ float sEm[3][320];            // triple-buffered 32-step em chunks
    __shared__ int   sB[128];                // per-jump-chunk boundary tags

    const int tid  = threadIdx.x;
    const int wid  = tid >> 5;
    const int lane = tid & 31;
    const int b    = blockIdx.x;
    const float* emb = g_em + (size_t)b * T_ * K_;
    const bool act = lane < K_;

    // per-lane transition column T[i][lane]
    float tc0=0,tc1=0,tc2=0,tc3=0,tc4=0,tc5=0,tc6=0,tc7=0,tc8=0;
    if (act) {
        tc0 = trans[0*K_+lane]; tc1 = trans[1*K_+lane]; tc2 = trans[2*K_+lane];
        tc3 = trans[3*K_+lane]; tc4 = trans[4*K_+lane]; tc5 = trans[5*K_+lane];
        tc6 = trans[6*K_+lane]; tc7 = trans[7*K_+lane]; tc8 = trans[8*K_+lane];
    }

    // prologue: stage em chunk 0 (t=1..32); warp0 computes + publishes s_0
    for (int i = tid; i < 288; i += 64) sEm[0][i] = emb[9 + i];
    float sv = 0.f;
    if (wid == 0) {
        if (act) {
            sv = st[lane] + emb[lane];          // reference add order
            sRing[0 * 12 + lane] = sv;          // slot of t=0
        }
    }
    __syncthreads();

    int ws  = 1;   // warp0: ring slot of next write (t=1)
    int sp0 = 0;   // warp1: ring slot of (t0-1) for next processed chunk

    for (int c = 0; c <= 256; ++c) {
        if (wid == 0 && c <= 255) {
            // prefetch em chunk c+1 into registers (off critical path)
            float pref[9];
            const int cn = c + 1;
            int nnext = 0;
            if (cn <= 255) nnext = min(32, 8191 - 32 * cn);
            const int t0n = 1 + 32 * cn;
            #pragma unroll
            for (int k = 0; k < 9; ++k) {
                int idx = lane + k * 32;
                pref[k] = (idx < nnext * 9) ? emb[(size_t)t0n * 9 + idx] : 0.f;
            }

            // compute score chain for chunk c
            const int ns = min(32, 8191 - 32 * c);
            const float* buf = sEm[c % 3];
            for (int q = 0; q < ns; ++q) {
                float e = buf[q * 9 + lane];        // padded: lane<32 safe
                float a0 = __shfl_sync(0xffffffffu, sv, 0) + tc0;
                float a1 = __shfl_sync(0xffffffffu, sv, 1) + tc1;
                float a2 = __shfl_sync(0xffffffffu, sv, 2) + tc2;
                float a3 = __shfl_sync(0xffffffffu, sv, 3) + tc3;
                float a4 = __shfl_sync(0xffffffffu, sv, 4) + tc4;
                float a5 = __shfl_sync(0xffffffffu, sv, 5) + tc5;
                float a6 = __shfl_sync(0xffffffffu, sv, 6) + tc6;
                float a7 = __shfl_sync(0xffffffffu, sv, 7) + tc7;
                float a8 = __shfl_sync(0xffffffffu, sv, 8) + tc8;
                float m = fmaxf(fmaxf(fmaxf(fmaxf(a0,a1), fmaxf(a2,a3)),
                                      fmaxf(fmaxf(a4,a5), fmaxf(a6,a7))), a8);
                sv = m + e;                          // == max(cd_with_e) bitwise
                if (act) sRing[ws * 12 + lane] = sv;
                ws = (ws + 1 == RSLOTS) ? 0 : ws + 1;
            }

            // store prefetched chunk
            if (cn <= 255) {
                float* nb2 = sEm[cn % 3];
                #pragma unroll
                for (int k = 0; k < 9; ++k) nb2[lane + k * 32] = pref[k];
            }
        }
        else if (wid == 1 && c >= 1) {
            const int cc = c - 1;
            const int t0 = 1 + 32 * cc;
            const int ns = min(32, 8191 - 32 * cc);
            const float* buf = sEm[cc % 3];
            int sp = sp0;
            for (int q = 0; q < ns; ++q) {
                float4 p0 = *(const float4*)&sRing[sp * 12];
                float4 p1 = *(const float4*)&sRing[sp * 12 + 4];
                float  s8 = sRing[sp * 12 + 8];
                int sc = (sp + 1 == RSLOTS) ? 0 : sp + 1;
                float m = sRing[sc * 12 + lane];     // s_t[lane] (garbage if !act)
                float e = buf[q * 9 + lane];
                // exact reference candidate values
                float cd0 = (p0.x + tc0) + e;
                float cd1 = (p0.y + tc1) + e;
                float cd2 = (p0.z + tc2) + e;
                float cd3 = (p0.w + tc3) + e;
                float cd4 = (p1.x + tc4) + e;
                float cd5 = (p1.y + tc5) + e;
                float cd6 = (p1.z + tc6) + e;
                float cd7 = (p1.w + tc7) + e;
                // first-max semantics (cd8 hit guaranteed if none earlier match)
                int bp = 8;
                bp = (cd7 == m) ? 7 : bp;
                bp = (cd6 == m) ? 6 : bp;
                bp = (cd5 == m) ? 5 : bp;
                bp = (cd4 == m) ? 4 : bp;
                bp = (cd3 == m) ? 3 : bp;
                bp = (cd2 == m) ? 2 : bp;
                bp = (cd1 == m) ? 1 : bp;
                bp = (cd0 == m) ? 0 : bp;
                int bpn = __shfl_down_sync(0xffffffffu, bp, 1);
                if (act && ((lane & 1) == 0)) {
                    unsigned char byte = (lane == 8)
                        ? (unsigned char)bp
                        : (unsigned char)(bp | (bpn << 4));
                    sBpN[(t0 + q) * 5 + (lane >> 1)] = byte;
                }
                sp = sc;
            }
            sp0 += 32; if (sp0 >= RSLOTS) sp0 -= RSLOTS;
        }
        __syncthreads();
    }

    // ---------------- backtrack: 3-phase parallel, exact chase -------------
    unsigned char* sMap = (unsigned char*)sRing;   // 1152 B alias over dead ring head
    // NOTE: final s vector lives at ring slot 8191 % 72 = 55 (byte offset 2640),
    // safely beyond the 1152-byte sMap region.

    // Phase A: jump-chunk maps. unit u = q*9 + j; chase t: thi(q)..64q+1.
    #pragma unroll 1
    for (int k = 0; k < 9; ++k) {
        int u1 = tid + 64 * k;
        int u2 = tid + 64 * (k + 9);
        int q1 = u1 / 9, j1 = u1 - q1 * 9;
        int q2 = u2 / 9, j2 = u2 - q2 * 9;
        int t1 = min(64 * q1 + 64, 8191), lo1 = 64 * q1;
        int t2 = min(64 * q2 + 64, 8191), lo2 = 64 * q2;
        int g1 = j1, g2 = j2;
        #pragma unroll 1
        for (int s = 0; s < 64; ++s) {
            if (t1 > lo1) { g1 = nib_get(sBpN, t1, g1); --t1; }
            if (t2 > lo2) { g2 = nib_get(sBpN, t2, g2); --t2; }
        }
        sMap[u1] = (unsigned char)g1;
        sMap[u2] = (unsigned char)g2;
    }
    __syncthreads();

    // Phase B (thread 0): final argmax + boundary-tag chain over 128 maps
    if (tid == 0) {
        const float* sf = &sRing[55 * 12];          // s_{8191}
        float best = sf[0] + et[0];
        int last = 0;
        #pragma unroll
        for (int j = 1; j < 9; ++j) {
            float v = sf[j] + et[j];
            if (v > best) { best = v; last = j; }   // strict > keeps first max
        }
        int tag = last;
        sB[127] = tag;
        for (int q = 127; q >= 1; --q) {
            tag = sMap[q * 9 + tag];
            sB[q - 1] = tag;
        }
    }
    __syncthreads();

    // Phase C: emit tags, 2 jump-chunks per thread
    float* ob = out + (size_t)b * T_;
    #pragma unroll 1
    for (int r = 0; r < 2; ++r) {
        int q = tid + 64 * r;
        int thi = min(64 * q + 64, 8191);
        int tlo = 64 * q;
        int tag = sB[q];
        if (q == 127) ob[8191] = (float)tag;
        for (int t = thi; t > tlo; --t) {
            tag = nib_get(sBpN, t, tag);
            ob[t - 1] = (float)tag;
        }
    }
}

// ---------------------------------------------------------------------------
extern "C" void kernel_launch(void* const* d_in, const int* in_sizes, int n_in,
                              void* d_out, int out_size)
{
    int ix = 0, iW1 = 1, ib1 = 2, iW2 = 3, ib2 = 4, iW3 = 5, itr = 9;
    int nine[3] = {6, 7, 8};
    int n9 = 0;
    for (int i = 0; i < n_in; ++i) {
        long long s = in_sizes[i];
        if (s == 67108864LL)      ix  = i;
        else if (s == 16384)      iW1 = i;
        else if (s == 128)        ib1 = i;
        else if (s == 8192)       iW2 = i;
        else if (s == 64)         ib2 = i;
        else if (s == 576)        iW3 = i;
        else if (s == 81)         itr = i;
        else if (s == 9) { if (n9 < 3) nine[n9++] = i; }
    }
    const float* x  = (const float*)d_in[ix];
    const float* W1 = (const float*)d_in[iW1];
    const float* b1 = (const float*)d_in[ib1];
    const float* W2 = (const float*)d_in[iW2];
    const float* b2 = (const float*)d_in[ib2];
    const float* W3 = (const float*)d_in[iW3];
    const float* b3 = (const float*)d_in[nine[0]];
    const float* st = (const float*)d_in[nine[1]];
    const float* et = (const float*)d_in[nine[2]];
    const float* tr = (const float*)d_in[itr];
    float* out = (float*)d_out;

    mlp_kernel<<<(B_ * T_) / TOK, 256>>>(x, W1, b1, W2, b2, W3, b3);
    viterbi_kernel<<<B_, 64>>>(st, et, tr, out);
}

// round 6
// speedup vs baseline: 1.2151x; 1.0170x over previous
#include <cuda_runtime.h>

#define B_  64
#define T_  8192
#define D_  128
#define H1_ 128
#define H2_ 64
#define K_  9

// Emissions scratch (B*T, K) fp32 = 18.9 MB (device global; no allocs allowed).
__device__ float g_em[(size_t)B_ * T_ * K_];

// ---------------------------------------------------------------------------
// packed f32x2 helpers (bitwise: each half is an independent RN fma)
// ---------------------------------------------------------------------------
__device__ __forceinline__ unsigned long long ffma2(
    unsigned long long a, unsigned long long b, unsigned long long c) {
    unsigned long long d;
    asm("fma.rn.f32x2 %0, %1, %2, %3;" : "=l"(d) : "l"(a), "l"(b), "l"(c));
    return d;
}
__device__ __forceinline__ unsigned long long dup2(float v) {
    unsigned long long d;
    asm("mov.b64 %0, {%1, %1};" : "=l"(d) : "f"(v));
    return d;
}
__device__ __forceinline__ float lo32(unsigned long long v) {
    return __uint_as_float((unsigned)(v & 0xffffffffull));
}
__device__ __forceinline__ float hi32(unsigned long long v) {
    return __uint_as_float((unsigned)(v >> 32));
}

// ---------------------------------------------------------------------------
// Kernel 1: fused MLP -> emissions. 64 tokens / block, 256 threads.
// Activations transposed in smem: sXT[d][tok], row stride 66 (8B-aligned pairs).
// Token pairs packed into f32x2; each accumulator keeps exact k-order.
// ---------------------------------------------------------------------------
#define TOK 64
#define XS  66   // transposed row stride (floats): even -> 8B aligned pairs

__global__ void __launch_bounds__(256) mlp_kernel(
    const float* __restrict__ x,  const float* __restrict__ W1, const float* __restrict__ b1,
    const float* __restrict__ W2, const float* __restrict__ b2,
    const float* __restrict__ W3, const float* __restrict__ b3)
{
    __shared__ float sXT[128 * XS];   // x^T -> h1^T -> h2^T (in-place, barrier-separated)
    __shared__ float sW[2048];        // W chunk (16 x 128 or 16 x 64)
    __shared__ float sW3[576];
    __shared__ float sB1[128];
    __shared__ float sB2[64];
    __shared__ float sB3[16];

    const int tid = threadIdx.x;
    const size_t nb = (size_t)blockIdx.x * TOK;

    // ---- load x tile transposed: sXT[d][tok] ----
    {
        const float4* xv = (const float4*)(x + nb * D_);
        #pragma unroll
        for (int it = 0; it < 8; ++it) {
            int v   = tid + it * 256;      // 0..2047 float4
            int tok = v >> 5;              // 32 float4 per token row
            int d   = (v & 31) * 4;
            float4 f = xv[v];
            sXT[(d + 0) * XS + tok] = f.x;
            sXT[(d + 1) * XS + tok] = f.y;
            sXT[(d + 2) * XS + tok] = f.z;
            sXT[(d + 3) * XS + tok] = f.w;
        }
    }
    if (tid < 128) sB1[tid] = b1[tid];
    if (tid < 64)  sB2[tid] = b2[tid];
    if (tid < 9)   sB3[tid] = b3[tid];
    for (int k = tid; k < 576; k += 256) sW3[k] = W3[k];

    // ================= stage 1: h1 = relu(x @ W1 + b1) =================
    // 32 tx (o0=tx*4) x 8 ty (t0=ty*8): 4 token-pairs x 4 outputs per thread.
    {
        const int tx = tid & 31, ty = tid >> 5;
        const int o0 = tx * 4, t0 = ty * 8;
        unsigned long long acc[4][4];
        #pragma unroll
        for (int p = 0; p < 4; ++p)
            #pragma unroll
            for (int j = 0; j < 4; ++j) acc[p][j] = 0ull;

        const float4* w1v = (const float4*)W1;
        float4* sWv = (float4*)sW;
        for (int pc = 0; pc < 8; ++pc) {          // 8 chunks of 16 k-rows
            __syncthreads();
            sWv[tid]       = w1v[pc * 512 + tid];
            sWv[tid + 256] = w1v[pc * 512 + tid + 256];
            __syncthreads();
            #pragma unroll
            for (int kl = 0; kl < 16; ++kl) {
                const int k = pc * 16 + kl;
                float4 w = *(const float4*)&sW[kl * 128 + o0];
                unsigned long long w0 = dup2(w.x), w1 = dup2(w.y),
                                   w2 = dup2(w.z), w3 = dup2(w.w);
                const unsigned long long* ap =
                    (const unsigned long long*)&sXT[k * XS + t0];
                unsigned long long a0 = ap[0], a1 = ap[1], a2 = ap[2], a3 = ap[3];
                acc[0][0] = ffma2(a0, w0, acc[0][0]);
                acc[0][1] = ffma2(a0, w1, acc[0][1]);
                acc[0][2] = ffma2(a0, w2, acc[0][2]);
                acc[0][3] = ffma2(a0, w3, acc[0][3]);
                acc[1][0] = ffma2(a1, w0, acc[1][0]);
                acc[1][1] = ffma2(a1, w1, acc[1][1]);
                acc[1][2] = ffma2(a1, w2, acc[1][2]);
                acc[1][3] = ffma2(a1, w3, acc[1][3]);
                acc[2][0] = ffma2(a2, w0, acc[2][0]);
                acc[2][1] = ffma2(a2, w1, acc[2][1]);
                acc[2][2] = ffma2(a2, w2, acc[2][2]);
                acc[2][3] = ffma2(a2, w3, acc[2][3]);
                acc[3][0] = ffma2(a3, w0, acc[3][0]);
                acc[3][1] = ffma2(a3, w1, acc[3][1]);
                acc[3][2] = ffma2(a3, w2, acc[3][2]);
                acc[3][3] = ffma2(a3, w3, acc[3][3]);
            }
        }
        __syncthreads();   // all reads of sXT (x) complete
        #pragma unroll
        for (int j = 0; j < 4; ++j) {
            float bb = sB1[o0 + j];
            #pragma unroll
            for (int p = 0; p < 4; ++p) {
                float v0 = lo32(acc[p][j]) + bb; v0 = v0 > 0.f ? v0 : 0.f;
                float v1 = hi32(acc[p][j]) + bb; v1 = v1 > 0.f ? v1 : 0.f;
                sXT[(o0 + j) * XS + t0 + 2 * p]     = v0;   // h1^T
                sXT[(o0 + j) * XS + t0 + 2 * p + 1] = v1;
            }
        }
    }

    // ================= stage 2: h2 = relu(h1 @ W2 + b2) =================
    // 16 tx (o0=tx*4) x 16 ty (t0=ty*4): 2 token-pairs x 4 outputs per thread.
    {
        const int tx = tid & 15, ty = tid >> 4;
        const int o0 = tx * 4, t0 = ty * 4;
        unsigned long long acc[2][4];
        #pragma unroll
        for (int p = 0; p < 2; ++p)
            #pragma unroll
            for (int j = 0; j < 4; ++j) acc[p][j] = 0ull;

        const float4* w2v = (const float4*)W2;
        float4* sWv = (float4*)sW;
        for (int pc = 0; pc < 8; ++pc) {
            __syncthreads();
            sWv[tid] = w2v[pc * 256 + tid];       // 16x64 = 256 float4
            __syncthreads();
            #pragma unroll
            for (int kl = 0; kl < 16; ++kl) {
                const int k = pc * 16 + kl;
                float4 w = *(const float4*)&sW[kl * 64 + o0];
                unsigned long long w0 = dup2(w.x), w1 = dup2(w.y),
                                   w2_ = dup2(w.z), w3 = dup2(w.w);
                const unsigned long long* ap =
                    (const unsigned long long*)&sXT[k * XS + t0];
                unsigned long long a0 = ap[0], a1 = ap[1];
                acc[0][0] = ffma2(a0, w0, acc[0][0]);
                acc[0][1] = ffma2(a0, w1, acc[0][1]);
                acc[0][2] = ffma2(a0, w2_, acc[0][2]);
                acc[0][3] = ffma2(a0, w3, acc[0][3]);
                acc[1][0] = ffma2(a1, w0, acc[1][0]);
                acc[1][1] = ffma2(a1, w1, acc[1][1]);
                acc[1][2] = ffma2(a1, w2_, acc[1][2]);
                acc[1][3] = ffma2(a1, w3, acc[1][3]);
            }
        }
        __syncthreads();   // all reads of sXT (h1) complete
        #pragma unroll
        for (int j = 0; j < 4; ++j) {
            float bb = sB2[o0 + j];
            #pragma unroll
            for (int p = 0; p < 2; ++p) {
                float v0 = lo32(acc[p][j]) + bb; v0 = v0 > 0.f ? v0 : 0.f;
                float v1 = hi32(acc[p][j]) + bb; v1 = v1 > 0.f ? v1 : 0.f;
                sXT[(o0 + j) * XS + t0 + 2 * p]     = v0;   // h2^T (rows 0..63)
                sXT[(o0 + j) * XS + t0 + 2 * p + 1] = v1;
            }
        }
    }
    __syncthreads();

    // ================= stage 3: em = h2 @ W3 + b3 (exact k-order) ==========
    if (tid < TOK) {
        const int tok = tid;
        float e[9];
        #pragma unroll
        for (int j = 0; j < 9; ++j) e[j] = 0.f;
        for (int k = 0; k < 64; ++k) {
            float h = sXT[k * XS + tok];
            #pragma unroll
            for (int j = 0; j < 9; ++j)
                e[j] = fmaf(h, sW3[k * 9 + j], e[j]);
        }
        float* dst = g_em + (nb + tok) * K_;
        #pragma unroll
        for (int j = 0; j < 9; ++j) dst[j] = e[j] + sB3[j];
    }
}

// ---------------------------------------------------------------------------
// Kernel 2: Viterbi. One block (4 warps) per batch element.
//   warp0: score chain (bitwise identical: RN monotone, fmax exact)
//   warps1-3: trail one chunk, each ~1/3 of its 32 steps; bp via mask+ffs
//   backtrack: 3-phase parallel jump-chunks (exact chase), 128 threads.
// ---------------------------------------------------------------------------
#define RSLOTS 72
#define RPAD   (RSLOTS * 12 + 32)

__device__ __forceinline__ int nib_get(const unsigned char* bpn, int t, int tag) {
    unsigned v = bpn[t * 5 + (tag >> 1)];
    return (int)((v >> ((tag & 1) * 4)) & 0xF);
}

__global__ void __launch_bounds__(128) viterbi_kernel(
    const float* __restrict__ st, const float* __restrict__ et,
    const float* __restrict__ trans, float* __restrict__ out)
{
    __shared__ unsigned char sBpN[T_ * 5];   // 40960 B nibble-packed backpointers
    __shared__ float sRing[RPAD];            // s-vector ring, 12 floats/slot
    __shared__ float sEm[3][320];            // triple-buffered 32-step em chunks
    __shared__ int   sB[128];                // jump-chunk boundary tags

    const int tid  = threadIdx.x;
    const int wid  = tid >> 5;
    const int lane = tid & 31;
    const int b    = blockIdx.x;
    const float* emb = g_em + (size_t)b * T_ * K_;
    const bool act = lane < K_;

    float tc0=0,tc1=0,tc2=0,tc3=0,tc4=0,tc5=0,tc6=0,tc7=0,tc8=0;
    if (act) {
        tc0 = trans[0*K_+lane]; tc1 = trans[1*K_+lane]; tc2 = trans[2*K_+lane];
        tc3 = trans[3*K_+lane]; tc4 = trans[4*K_+lane]; tc5 = trans[5*K_+lane];
        tc6 = trans[6*K_+lane]; tc7 = trans[7*K_+lane]; tc8 = trans[8*K_+lane];
    }

    // prologue: stage em chunk 0 (t=1..32); warp0 publishes s_0
    for (int i = tid; i < 288; i += 128) sEm[0][i] = emb[9 + i];
    float sv = 0.f;
    if (wid == 0 && act) {
        sv = st[lane] + emb[lane];              // reference add order
        sRing[0 * 12 + lane] = sv;
    }
    __syncthreads();

    int ws  = 1;   // warp0: ring slot of next write (t=1)
    int sp0 = 0;   // consumers: ring slot of (t0-1) for next processed chunk

    for (int c = 0; c <= 256; ++c) {
        if (wid == 0) {
            if (c <= 255) {
                // prefetch em chunk c+1 into registers (off critical path)
                float pref[9];
                const int cn = c + 1;
                int nnext = 0;
                if (cn <= 255) nnext = min(32, 8191 - 32 * cn);
                const int t0n = 1 + 32 * cn;
                #pragma unroll
                for (int k = 0; k < 9; ++k) {
                    int idx = lane + k * 32;
                    pref[k] = (idx < nnext * 9) ? emb[(size_t)t0n * 9 + idx] : 0.f;
                }

                const int ns = min(32, 8191 - 32 * c);
                const float* buf = sEm[c % 3];
                #pragma unroll 2
                for (int q = 0; q < ns; ++q) {
                    float e = buf[q * 9 + lane];
                    float a0 = __shfl_sync(0xffffffffu, sv, 0) + tc0;
                    float a1 = __shfl_sync(0xffffffffu, sv, 1) + tc1;
                    float a2 = __shfl_sync(0xffffffffu, sv, 2) + tc2;
                    float a3 = __shfl_sync(0xffffffffu, sv, 3) + tc3;
                    float a4 = __shfl_sync(0xffffffffu, sv, 4) + tc4;
                    float a5 = __shfl_sync(0xffffffffu, sv, 5) + tc5;
                    float a6 = __shfl_sync(0xffffffffu, sv, 6) + tc6;
                    float a7 = __shfl_sync(0xffffffffu, sv, 7) + tc7;
                    float a8 = __shfl_sync(0xffffffffu, sv, 8) + tc8;
                    float m = fmaxf(fmaxf(fmaxf(fmaxf(a0,a1), fmaxf(a2,a3)),
                                          fmaxf(fmaxf(a4,a5), fmaxf(a6,a7))), a8);
                    sv = m + e;                   // == max(cd_with_e) bitwise
                    if (act) sRing[ws * 12 + lane] = sv;
                    ws = (ws + 1 == RSLOTS) ? 0 : ws + 1;
                }
                if (cn <= 255) {
                    float* nb2 = sEm[cn % 3];
                    #pragma unroll
                    for (int k = 0; k < 9; ++k) nb2[lane + k * 32] = pref[k];
                }
            }
        }
        else if (c >= 1) {
            const int cc = c - 1;
            const int t0 = 1 + 32 * cc;
            const int ns = min(32, 8191 - 32 * cc);
            int qlo = 11 * (wid - 1);
            int qhi = (wid == 3) ? ns : min(11 * wid, ns);
            if (qlo > ns) qlo = ns;
            const float* buf = sEm[cc % 3];
            int sp = sp0 + qlo; if (sp >= RSLOTS) sp -= RSLOTS;
            for (int q = qlo; q < qhi; ++q) {
                float4 p0 = *(const float4*)&sRing[sp * 12];
                float4 p1 = *(const float4*)&sRing[sp * 12 + 4];
                float  s8 = sRing[sp * 12 + 8];
                int sc = (sp + 1 == RSLOTS) ? 0 : sp + 1;
                float m = sRing[sc * 12 + lane];     // s_t[lane]
                float e = buf[q * 9 + lane];
                float cd0 = (p0.x + tc0) + e;        // exact reference order
                float cd1 = (p0.y + tc1) + e;
                float cd2 = (p0.z + tc2) + e;
                float cd3 = (p0.w + tc3) + e;
                float cd4 = (p1.x + tc4) + e;
                float cd5 = (p1.y + tc5) + e;
                float cd6 = (p1.z + tc6) + e;
                float cd7 = (p1.w + tc7) + e;
                float cd8 = (s8   + tc8) + e;
                unsigned mk = (cd0 == m ? 1u   : 0u) | (cd1 == m ? 2u   : 0u)
                            | (cd2 == m ? 4u   : 0u) | (cd3 == m ? 8u   : 0u)
                            | (cd4 == m ? 16u  : 0u) | (cd5 == m ? 32u  : 0u)
                            | (cd6 == m ? 64u  : 0u) | (cd7 == m ? 128u : 0u)
                            | (cd8 == m ? 256u : 0u);
                int bp = __ffs(mk) - 1;              // first-max (jnp.argmax)
                int bpn = __shfl_down_sync(0xffffffffu, bp, 1);
                if (act && ((lane & 1) == 0)) {
                    unsigned char byte = (lane == 8)
                        ? (unsigned char)bp
                        : (unsigned char)(bp | (bpn << 4));
                    sBpN[(t0 + q) * 5 + (lane >> 1)] = byte;
                }
                sp = sc;
            }
        }
        if (c >= 1) { sp0 += 32; if (sp0 >= RSLOTS) sp0 -= RSLOTS; }
        __syncthreads();
    }

    // ---------------- backtrack: 3-phase parallel, exact chase -------------
    unsigned char* sMap = (unsigned char*)sRing;   // 1152 B alias (slots 0..23)
    // final s vector lives at slot 8191 % 72 = 55 (byte 2640) — not aliased.

    // Phase A: 1152 units (128 chunks x 9 tags), 3 interleaved chases/thread.
    #pragma unroll 1
    for (int k = 0; k < 3; ++k) {
        int u1 = tid + 128 * k;
        int u2 = tid + 128 * (k + 3);
        int u3 = tid + 128 * (k + 6);
        int q1 = u1 / 9, j1 = u1 - q1 * 9;
        int q2 = u2 / 9, j2 = u2 - q2 * 9;
        int q3 = u3 / 9, j3 = u3 - q3 * 9;
        int t1 = min(64 * q1 + 64, 8191), lo1 = 64 * q1;
        int t2 = min(64 * q2 + 64, 8191), lo2 = 64 * q2;
        int t3 = min(64 * q3 + 64, 8191), lo3 = 64 * q3;
        int g1 = j1, g2 = j2, g3 = j3;
        #pragma unroll 1
        for (int s = 0; s < 64; ++s) {
            if (t1 > lo1) { g1 = nib_get(sBpN, t1, g1); --t1; }
            if (t2 > lo2) { g2 = nib_get(sBpN, t2, g2); --t2; }
            if (t3 > lo3) { g3 = nib_get(sBpN, t3, g3); --t3; }
        }
        sMap[u1] = (unsigned char)g1;
        sMap[u2] = (unsigned char)g2;
        sMap[u3] = (unsigned char)g3;
    }
    __syncthreads();

    // Phase B (thread 0): final argmax + boundary chain over 128 maps
    if (tid == 0) {
        const float* sf = &sRing[55 * 12];          // s_{8191}
        float best = sf[0] + et[0];
        int last = 0;
        #pragma unroll
        for (int j = 1; j < 9; ++j) {
            float v = sf[j] + et[j];
            if (v > best) { best = v; last = j; }   // strict >: first max
        }
        int tag = last;
        sB[127] = tag;
        for (int q = 127; q >= 1; --q) {
            tag = sMap[q * 9 + tag];
            sB[q - 1] = tag;
        }
    }
    __syncthreads();

    // Phase C: emit tags, one jump-chunk per thread
    float* ob = out + (size_t)b * T_;
    {
        int q = tid;
        int thi = min(64 * q + 64, 8191);
        int tlo = 64 * q;
        int tag = sB[q];
        if (q == 127) ob[8191] = (float)tag;
        for (int t = thi; t > tlo; --t) {
            tag = nib_get(sBpN, t, tag);
            ob[t - 1] = (float)tag;
        }
    }
}

// ---------------------------------------------------------------------------
extern "C" void kernel_launch(void* const* d_in, const int* in_sizes, int n_in,
                              void* d_out, int out_size)
{
    int ix = 0, iW1 = 1, ib1 = 2, iW2 = 3, ib2 = 4, iW3 = 5, itr = 9;
    int nine[3] = {6, 7, 8};
    int n9 = 0;
    for (int i = 0; i < n_in; ++i) {
        long long s = in_sizes[i];
        if (s == 67108864LL)      ix  = i;
        else if (s == 16384)      iW1 = i;
        else if (s == 128)        ib1 = i;
        else if (s == 8192)       iW2 = i;
        else if (s == 64)         ib2 = i;
        else if (s == 576)        iW3 = i;
        else if (s == 81)         itr = i;
        else if (s == 9) { if (n9 < 3) nine[n9++] = i; }
    }
    const float* x  = (const float*)d_in[ix];
    const float* W1 = (const float*)d_in[iW1];
    const float* b1 = (const float*)d_in[ib1];
    const float* W2 = (const float*)d_in[iW2];
    const float* b2 = (const float*)d_in[ib2];
    const float* W3 = (const float*)d_in[iW3];
    const float* b3 = (const float*)d_in[nine[0]];
    const float* st = (const float*)d_in[nine[1]];
    const float* et = (const float*)d_in[nine[2]];
    const float* tr = (const float*)d_in[itr];
    float* out = (float*)d_out;

    mlp_kernel<<<(B_ * T_) / TOK, 256>>>(x, W1, b1, W2, b2, W3, b3);
    viterbi_kernel<<<B_, 128>>>(st, et, tr, out);
}